// round 4
// baseline (speedup 1.0000x reference)
#include <cuda_runtime.h>
#include <cuda_bf16.h>
#include <cstdint>

#define NDIM   512
#define BK     32
#define NCH    (NDIM / BK)          // 16
#define CTA_M  128
#define CTA_N  128
#define NTHREADS 256
#define ROWB   80                   // padded smem row stride (40 bf16)
#define TILEB  (128 * ROWB)         // 10240 B
#define STG_ALO (1 * TILEB)
#define STG_BHI (2 * TILEB)
#define STG_BLO (3 * TILEB)
#define STAGE_BYTES (4 * TILEB)     // 40960
#define SMEM_TOTAL  (2 * STAGE_BYTES)
#define THRESH 2e-4f

// ---- device scratch (prep output) ----
__device__ float         g_WT [NDIM * NDIM];   // W^T (n,k), diag=0, fp32 (fixup)
__device__ __nv_bfloat16 g_Whi[NDIM * NDIM];   // (n,k) bf16 hi
__device__ __nv_bfloat16 g_Wlo[NDIM * NDIM];   // (n,k) bf16 lo

__device__ __forceinline__ uint32_t smem_u32(const void* p) {
    uint32_t a;
    asm("{ .reg .u64 t; cvta.to.shared.u64 t, %1; cvt.u32.u64 %0, t; }" : "=r"(a) : "l"(p));
    return a;
}

__device__ __forceinline__ void mma_bf16(float* c, const uint32_t* a,
                                         uint32_t b0, uint32_t b1) {
    asm volatile(
        "mma.sync.aligned.m16n8k16.row.col.f32.bf16.bf16.f32 "
        "{%0,%1,%2,%3}, {%4,%5,%6,%7}, {%8,%9}, {%0,%1,%2,%3};\n"
        : "+f"(c[0]), "+f"(c[1]), "+f"(c[2]), "+f"(c[3])
        : "r"(a[0]), "r"(a[1]), "r"(a[2]), "r"(a[3]), "r"(b0), "r"(b1));
}

#define CP16(dst, src) \
    asm volatile("cp.async.cg.shared.global [%0], [%1], 16;\n" :: "r"(dst), "l"(src))
#define CP_COMMIT()  asm volatile("cp.async.commit_group;\n" ::: "memory")
#define CP_WAIT0()   asm volatile("cp.async.wait_group 0;\n" ::: "memory")

__device__ __forceinline__ uint32_t pack_bf2(float lo_elem, float hi_elem) {
    __nv_bfloat162 h = __floats2bfloat162_rn(lo_elem, hi_elem); // .x in lower 16
    return *reinterpret_cast<uint32_t*>(&h);
}

// ============================ prep ============================
__global__ void prep_w(const float* __restrict__ W) {
    int idx = blockIdx.x * blockDim.x + threadIdx.x;   // n*512 + k
    int n = idx >> 9, k = idx & (NDIM - 1);
    float w = (k == n) ? 0.0f : W[(size_t)k * NDIM + n];
    g_WT[idx] = w;
    __nv_bfloat16 hi = __float2bfloat16_rn(w);
    g_Whi[idx] = hi;
    g_Wlo[idx] = __float2bfloat16_rn(w - __bfloat162float(hi));
}

// ============================ main ============================
__global__ __launch_bounds__(NTHREADS, 2)
void li_mma_kernel(const float* __restrict__ X,
                   const float* __restrict__ bias,
                   float* __restrict__ out)
{
    extern __shared__ char smem[];
    const uint32_t sb = smem_u32(smem);
    const int tid = threadIdx.x;
    const int lid = tid & 31;
    const int wid = tid >> 5;
    const int wm  = wid >> 2;          // 0..1 -> m offset 64
    const int wn  = wid & 3;           // 0..3 -> n offset 32
    const int g   = lid >> 2;          // 0..7
    const int t   = lid & 3;           // 0..3
    const int cta_n = blockIdx.x * CTA_N;
    const size_t cta_m = (size_t)blockIdx.y * CTA_M;

    // A producer mapping: row ar, k-half ah (16 floats each)
    const int ar = tid >> 1;
    const int ah = tid & 1;
    const float* xsrc = X + (cta_m + ar) * NDIM + ah * 16;

    float acc[4][4][4];
    #pragma unroll
    for (int a = 0; a < 4; ++a)
        #pragma unroll
        for (int b = 0; b < 4; ++b)
            #pragma unroll
            for (int c = 0; c < 4; ++c) acc[a][b][c] = 0.0f;

    // ---- helpers as lambdas ----
    auto copyB = [&](int chunk, int s) {
        const char* hsrc = (const char*)g_Whi;
        const char* lsrc = (const char*)g_Wlo;
        #pragma unroll
        for (int q = 0; q < 2; ++q) {
            int idx = tid + q * NTHREADS;        // 0..511
            int row = idx >> 2, c4 = idx & 3;
            size_t goff = ((size_t)(cta_n + row) * NDIM + chunk * BK) * 2 + c4 * 16;
            uint32_t doff = (uint32_t)s * STAGE_BYTES + row * ROWB + c4 * 16;
            CP16(sb + STG_BHI + doff, hsrc + goff);
            CP16(sb + STG_BLO + doff, lsrc + goff);
        }
        CP_COMMIT();
    };

    auto storeA = [&](int s, const float4* xa) {
        char* pH = smem + s * STAGE_BYTES + ar * ROWB + ah * 32;
        char* pL = pH + STG_ALO;
        uint32_t hw[8], lw[8];
        #pragma unroll
        for (int j = 0; j < 4; ++j) {
            float e0 = xa[j].x, e1 = xa[j].y, e2 = xa[j].z, e3 = xa[j].w;
            __nv_bfloat162 h01 = __floats2bfloat162_rn(e0, e1);
            __nv_bfloat162 h23 = __floats2bfloat162_rn(e2, e3);
            hw[2 * j]     = *reinterpret_cast<uint32_t*>(&h01);
            hw[2 * j + 1] = *reinterpret_cast<uint32_t*>(&h23);
            lw[2 * j]     = pack_bf2(e0 - __bfloat162float(h01.x),
                                     e1 - __bfloat162float(h01.y));
            lw[2 * j + 1] = pack_bf2(e2 - __bfloat162float(h23.x),
                                     e3 - __bfloat162float(h23.y));
        }
        *reinterpret_cast<uint4*>(pH)      = make_uint4(hw[0], hw[1], hw[2], hw[3]);
        *reinterpret_cast<uint4*>(pH + 16) = make_uint4(hw[4], hw[5], hw[6], hw[7]);
        *reinterpret_cast<uint4*>(pL)      = make_uint4(lw[0], lw[1], lw[2], lw[3]);
        *reinterpret_cast<uint4*>(pL + 16) = make_uint4(lw[4], lw[5], lw[6], lw[7]);
    };

    auto compute = [&](int s) {
        const char* base = smem + s * STAGE_BYTES;
        #pragma unroll
        for (int ks = 0; ks < 2; ++ks) {
            uint32_t bh[4][2], bl[4][2];
            #pragma unroll
            for (int nt = 0; nt < 4; ++nt) {
                int nrow = wn * 32 + nt * 8 + g;
                const char* pb = base + STG_BHI + nrow * ROWB + ks * 32 + t * 4;
                bh[nt][0] = *(const uint32_t*)pb;
                bh[nt][1] = *(const uint32_t*)(pb + 16);
                const char* pl = pb + (STG_BLO - STG_BHI);
                bl[nt][0] = *(const uint32_t*)pl;
                bl[nt][1] = *(const uint32_t*)(pl + 16);
            }
            #pragma unroll
            for (int mt = 0; mt < 4; ++mt) {
                int mrow = wm * 64 + mt * 16 + g;
                const char* pa = base + mrow * ROWB + ks * 32 + t * 4;
                uint32_t Ah[4], Al[4];
                Ah[0] = *(const uint32_t*)pa;
                Ah[1] = *(const uint32_t*)(pa + 8 * ROWB);
                Ah[2] = *(const uint32_t*)(pa + 16);
                Ah[3] = *(const uint32_t*)(pa + 8 * ROWB + 16);
                const char* pal = pa + STG_ALO;
                Al[0] = *(const uint32_t*)pal;
                Al[1] = *(const uint32_t*)(pal + 8 * ROWB);
                Al[2] = *(const uint32_t*)(pal + 16);
                Al[3] = *(const uint32_t*)(pal + 8 * ROWB + 16);
                #pragma unroll
                for (int nt = 0; nt < 4; ++nt) {
                    mma_bf16(acc[mt][nt], Ah, bh[nt][0], bh[nt][1]);
                    mma_bf16(acc[mt][nt], Al, bh[nt][0], bh[nt][1]);
                    mma_bf16(acc[mt][nt], Ah, bl[nt][0], bl[nt][1]);
                }
            }
        }
    };

    // ---- prologue: fill stage 0 ----
    {
        copyB(0, 0);
        float4 xa[4];
        #pragma unroll
        for (int j = 0; j < 4; ++j)
            xa[j] = *reinterpret_cast<const float4*>(xsrc + j * 4);
        storeA(0, xa);
        CP_WAIT0();
        __syncthreads();
    }

    // ---- mainloop ----
    for (int i = 0; i < NCH; ++i) {
        const int s = i & 1;
        float4 xa[4];
        if (i < NCH - 1) {
            copyB(i + 1, s ^ 1);
            const float* xs = xsrc + (i + 1) * BK;
            #pragma unroll
            for (int j = 0; j < 4; ++j)
                xa[j] = *reinterpret_cast<const float4*>(xs + j * 4);
        }
        compute(s);
        if (i < NCH - 1) {
            storeA(s ^ 1, xa);
            CP_WAIT0();
            __syncthreads();
        }
    }

    // ---- epilogue: bias + gate (+ exact fixup for tiny |inhib|) ----
    #pragma unroll
    for (int mt = 0; mt < 4; ++mt) {
        #pragma unroll
        for (int nt = 0; nt < 4; ++nt) {
            const int gcol = cta_n + wn * 32 + nt * 8 + 2 * t;
            const float b0 = bias[gcol], b1 = bias[gcol + 1];
            #pragma unroll
            for (int half = 0; half < 2; ++half) {
                const size_t grow = cta_m + wm * 64 + mt * 16 + g + half * 8;
                float v0 = acc[mt][nt][half * 2 + 0] + b0;
                float v1 = acc[mt][nt][half * 2 + 1] + b1;
                if (fabsf(v0) < THRESH) {
                    const float* xr = X + grow * NDIM;
                    const float* wr = g_WT + (size_t)gcol * NDIM;
                    float a = 0.0f;
                    #pragma unroll 1
                    for (int k = 0; k < NDIM; ++k) a = fmaf(xr[k], wr[k], a);
                    v0 = a + b0;
                }
                if (fabsf(v1) < THRESH) {
                    const float* xr = X + grow * NDIM;
                    const float* wr = g_WT + (size_t)(gcol + 1) * NDIM;
                    float a = 0.0f;
                    #pragma unroll 1
                    for (int k = 0; k < NDIM; ++k) a = fmaf(xr[k], wr[k], a);
                    v1 = a + b1;
                }
                const float2 xv = *reinterpret_cast<const float2*>(
                    X + grow * NDIM + gcol);
                float2 o;
                o.x = v0 > 0.0f ? xv.x : 0.0f;
                o.y = v1 > 0.0f ? xv.y : 0.0f;
                *reinterpret_cast<float2*>(out + grow * NDIM + gcol) = o;
            }
        }
    }
}

// ============================ host ============================
extern "C" void kernel_launch(void* const* d_in, const int* in_sizes, int n_in,
                              void* d_out, int out_size)
{
    const float* X    = (const float*)d_in[0];
    const float* W    = (const float*)d_in[1];
    const float* bias = (const float*)d_in[2];
    float* out = (float*)d_out;
    const int M = in_sizes[0] / NDIM;   // 32768

    prep_w<<<(NDIM * NDIM) / 256, 256>>>(W);

    cudaFuncSetAttribute(li_mma_kernel,
                         cudaFuncAttributeMaxDynamicSharedMemorySize, SMEM_TOTAL);
    dim3 grid(NDIM / CTA_N, M / CTA_M);   // (4, 256)
    li_mma_kernel<<<grid, NTHREADS, SMEM_TOTAL>>>(X, bias, out);
}

// round 5
// speedup vs baseline: 1.0196x; 1.0196x over previous
#include <cuda_runtime.h>
#include <cuda_bf16.h>
#include <cstdint>

#define NDIM   512
#define BK     32
#define NCH    (NDIM / BK)          // 16
#define CTA_M  128
#define CTA_N  128
#define NTHREADS 256
#define ROWB   80                   // padded smem row stride in bytes (32 bf16 + pad)
#define TILEB  (128 * ROWB)         // 10240 B
#define STG_ALO (1 * TILEB)
#define STG_BHI (2 * TILEB)
#define STG_BLO (3 * TILEB)
#define STAGE_BYTES (4 * TILEB)     // 40960
#define SMEM_TOTAL  (2 * STAGE_BYTES)
#define THRESH 2e-4f
#define MMAX   32768

// ---- device scratch (prep output) ----
__device__ float         g_WT [NDIM * NDIM];   // W^T (n,k), diag=0, fp32 (fixup)
__device__ __nv_bfloat16 g_Whi[NDIM * NDIM];   // (n,k) bf16 hi
__device__ __nv_bfloat16 g_Wlo[NDIM * NDIM];   // (n,k) bf16 lo
__device__ __nv_bfloat16 g_Xhi[(size_t)MMAX * NDIM];
__device__ __nv_bfloat16 g_Xlo[(size_t)MMAX * NDIM];

__device__ __forceinline__ uint32_t smem_u32(const void* p) {
    uint32_t a;
    asm("{ .reg .u64 t; cvta.to.shared.u64 t, %1; cvt.u32.u64 %0, t; }" : "=r"(a) : "l"(p));
    return a;
}
__device__ __forceinline__ void mma_bf16(float* c, const uint32_t* a,
                                         uint32_t b0, uint32_t b1) {
    asm volatile(
        "mma.sync.aligned.m16n8k16.row.col.f32.bf16.bf16.f32 "
        "{%0,%1,%2,%3}, {%4,%5,%6,%7}, {%8,%9}, {%0,%1,%2,%3};\n"
        : "+f"(c[0]), "+f"(c[1]), "+f"(c[2]), "+f"(c[3])
        : "r"(a[0]), "r"(a[1]), "r"(a[2]), "r"(a[3]), "r"(b0), "r"(b1));
}
__device__ __forceinline__ void ldmx4(uint32_t* r, uint32_t addr) {
    asm volatile("ldmatrix.sync.aligned.m8n8.x4.shared.b16 {%0,%1,%2,%3}, [%4];"
        : "=r"(r[0]), "=r"(r[1]), "=r"(r[2]), "=r"(r[3]) : "r"(addr));
}
#define CP16(dst, src) \
    asm volatile("cp.async.cg.shared.global [%0], [%1], 16;\n" :: "r"(dst), "l"(src))
#define CP_COMMIT()  asm volatile("cp.async.commit_group;\n" ::: "memory")
#define CP_WAIT0()   asm volatile("cp.async.wait_group 0;\n" ::: "memory")
#define CP_WAIT1()   asm volatile("cp.async.wait_group 1;\n" ::: "memory")

__device__ __forceinline__ uint32_t u32of(__nv_bfloat162 h) {
    return *reinterpret_cast<uint32_t*>(&h);
}

// ============================ prep ============================
__global__ void prep_w(const float* __restrict__ W) {
    int idx = blockIdx.x * blockDim.x + threadIdx.x;   // n*512 + k
    int n = idx >> 9, k = idx & (NDIM - 1);
    float w = (k == n) ? 0.0f : W[(size_t)k * NDIM + n];
    g_WT[idx] = w;
    __nv_bfloat16 hi = __float2bfloat16_rn(w);
    g_Whi[idx] = hi;
    g_Wlo[idx] = __float2bfloat16_rn(w - __bfloat162float(hi));
}

__global__ void prep_x(const float* __restrict__ X, int total4) {
    int idx = blockIdx.x * blockDim.x + threadIdx.x;
    if (idx >= total4) return;
    float4 v = reinterpret_cast<const float4*>(X)[idx];
    __nv_bfloat162 h01 = __floats2bfloat162_rn(v.x, v.y);
    __nv_bfloat162 h23 = __floats2bfloat162_rn(v.z, v.w);
    __nv_bfloat162 l01 = __floats2bfloat162_rn(v.x - __bfloat162float(h01.x),
                                               v.y - __bfloat162float(h01.y));
    __nv_bfloat162 l23 = __floats2bfloat162_rn(v.z - __bfloat162float(h23.x),
                                               v.w - __bfloat162float(h23.y));
    reinterpret_cast<uint2*>(g_Xhi)[idx] = make_uint2(u32of(h01), u32of(h23));
    reinterpret_cast<uint2*>(g_Xlo)[idx] = make_uint2(u32of(l01), u32of(l23));
}

// ============================ main ============================
__global__ __launch_bounds__(NTHREADS, 2)
void li_mma_kernel(const float* __restrict__ X,
                   const float* __restrict__ bias,
                   float* __restrict__ out)
{
    extern __shared__ char smem[];
    const uint32_t sb = smem_u32(smem);
    const int tid = threadIdx.x;
    const int lid = tid & 31;
    const int wid = tid >> 5;
    const int wm  = wid >> 2;          // 0..1 -> m offset 64
    const int wn  = wid & 3;           // 0..3 -> n offset 32
    const int g   = lid >> 2;          // 0..7
    const int t   = lid & 3;           // 0..3
    const int q   = lid >> 3;          // 0..3 (ldmatrix quad)
    const int rl  = lid & 7;           // 0..7
    const int cta_n = blockIdx.x * CTA_N;
    const size_t cta_m = (size_t)blockIdx.y * CTA_M;

    float acc[4][4][4];
    #pragma unroll
    for (int a = 0; a < 4; ++a)
        #pragma unroll
        for (int b = 0; b < 4; ++b)
            #pragma unroll
            for (int c = 0; c < 4; ++c) acc[a][b][c] = 0.0f;

    auto loadStage = [&](int chunk, int s) {
        const uint32_t st = sb + (uint32_t)s * STAGE_BYTES;
        const char* xh = (const char*)g_Xhi;
        const char* xl = (const char*)g_Xlo;
        const char* wh = (const char*)g_Whi;
        const char* wl = (const char*)g_Wlo;
        #pragma unroll
        for (int j = 0; j < 2; ++j) {
            int c = tid + j * NTHREADS;       // 0..511
            int row = c >> 2, c4 = c & 3;
            uint32_t doff = row * ROWB + c4 * 16;
            size_t gA = ((cta_m + row) * NDIM + (size_t)chunk * BK) * 2 + c4 * 16;
            size_t gB = (((size_t)cta_n + row) * NDIM + (size_t)chunk * BK) * 2 + c4 * 16;
            CP16(st + doff,            xh + gA);
            CP16(st + STG_ALO + doff,  xl + gA);
            CP16(st + STG_BHI + doff,  wh + gB);
            CP16(st + STG_BLO + doff,  wl + gB);
        }
        CP_COMMIT();
    };

    auto compute = [&](int s) {
        const uint32_t st = sb + (uint32_t)s * STAGE_BYTES;
        #pragma unroll
        for (int ks = 0; ks < 2; ++ks) {
            // --- B fragments via ldmatrix.x4: two nt tiles per call ---
            uint32_t bh[4][2], bl[4][2];
            #pragma unroll
            for (int ntp = 0; ntp < 2; ++ntp) {
                uint32_t baddr = st + STG_BHI
                    + (uint32_t)(wn * 32 + (ntp * 2 + (q >> 1)) * 8 + rl) * ROWB
                    + ks * 32 + (q & 1) * 16;
                uint32_t rr[4];
                ldmx4(rr, baddr);
                bh[2 * ntp][0] = rr[0]; bh[2 * ntp][1] = rr[1];
                bh[2 * ntp + 1][0] = rr[2]; bh[2 * ntp + 1][1] = rr[3];
                ldmx4(rr, baddr + (STG_BLO - STG_BHI));
                bl[2 * ntp][0] = rr[0]; bl[2 * ntp][1] = rr[1];
                bl[2 * ntp + 1][0] = rr[2]; bl[2 * ntp + 1][1] = rr[3];
            }
            // --- A fragments + MMAs ---
            #pragma unroll
            for (int mt = 0; mt < 4; ++mt) {
                uint32_t aaddr = st
                    + (uint32_t)(wm * 64 + mt * 16 + (q & 1) * 8 + rl) * ROWB
                    + ks * 32 + (q >> 1) * 16;
                uint32_t Ah[4], Al[4];
                ldmx4(Ah, aaddr);
                ldmx4(Al, aaddr + STG_ALO);
                #pragma unroll
                for (int nt = 0; nt < 4; ++nt) {
                    mma_bf16(acc[mt][nt], Ah, bh[nt][0], bh[nt][1]);
                    mma_bf16(acc[mt][nt], Al, bh[nt][0], bh[nt][1]);
                    mma_bf16(acc[mt][nt], Ah, bl[nt][0], bl[nt][1]);
                }
            }
        }
    };

    // ---- pipeline ----
    loadStage(0, 0);
    loadStage(1, 1);
    for (int i = 0; i < NCH; ++i) {
        const int s = i & 1;
        if (i < NCH - 1) { CP_WAIT1(); } else { CP_WAIT0(); }
        __syncthreads();
        compute(s);
        if (i + 2 < NCH) {
            __syncthreads();
            loadStage(i + 2, s);
        }
    }

    // ---- epilogue: bias + gate (+ exact fixup for tiny |inhib|) ----
    #pragma unroll
    for (int mt = 0; mt < 4; ++mt) {
        #pragma unroll
        for (int nt = 0; nt < 4; ++nt) {
            const int gcol = cta_n + wn * 32 + nt * 8 + 2 * t;
            const float b0 = bias[gcol], b1 = bias[gcol + 1];
            #pragma unroll
            for (int half = 0; half < 2; ++half) {
                const size_t grow = cta_m + wm * 64 + mt * 16 + g + half * 8;
                float v0 = acc[mt][nt][half * 2 + 0] + b0;
                float v1 = acc[mt][nt][half * 2 + 1] + b1;
                if (fabsf(v0) < THRESH) {
                    const float* xr = X + grow * NDIM;
                    const float* wr = g_WT + (size_t)gcol * NDIM;
                    float a = 0.0f;
                    #pragma unroll 1
                    for (int k = 0; k < NDIM; ++k) a = fmaf(xr[k], wr[k], a);
                    v0 = a + b0;
                }
                if (fabsf(v1) < THRESH) {
                    const float* xr = X + grow * NDIM;
                    const float* wr = g_WT + (size_t)(gcol + 1) * NDIM;
                    float a = 0.0f;
                    #pragma unroll 1
                    for (int k = 0; k < NDIM; ++k) a = fmaf(xr[k], wr[k], a);
                    v1 = a + b1;
                }
                const float2 xv = *reinterpret_cast<const float2*>(
                    X + grow * NDIM + gcol);
                float2 o;
                o.x = v0 > 0.0f ? xv.x : 0.0f;
                o.y = v1 > 0.0f ? xv.y : 0.0f;
                *reinterpret_cast<float2*>(out + grow * NDIM + gcol) = o;
            }
        }
    }
}

// ============================ host ============================
extern "C" void kernel_launch(void* const* d_in, const int* in_sizes, int n_in,
                              void* d_out, int out_size)
{
    const float* X    = (const float*)d_in[0];
    const float* W    = (const float*)d_in[1];
    const float* bias = (const float*)d_in[2];
    float* out = (float*)d_out;
    const int M = in_sizes[0] / NDIM;   // 32768

    prep_w<<<(NDIM * NDIM) / 256, 256>>>(W);
    const int total4 = M * NDIM / 4;
    prep_x<<<(total4 + 255) / 256, 256>>>(X, total4);

    cudaFuncSetAttribute(li_mma_kernel,
                         cudaFuncAttributeMaxDynamicSharedMemorySize, SMEM_TOTAL);
    dim3 grid(NDIM / CTA_N, M / CTA_M);   // (4, 256)
    li_mma_kernel<<<grid, NTHREADS, SMEM_TOTAL>>>(X, bias, out);
}

// round 6
// speedup vs baseline: 2.4258x; 2.3791x over previous
#include <cuda_runtime.h>
#include <cuda_fp16.h>
#include <cstdint>

#define NDIM   512
#define BK     32
#define NCH    (NDIM / BK)          // 16
#define CTA_M  128
#define CTA_N  128
#define NTHREADS 256
#define ROWB   80                   // padded smem row stride (32 fp16 = 64B + 16B pad)
#define TILEB  (128 * ROWB)         // 10240 B
#define STAGE_BYTES (2 * TILEB)     // A + B = 20480
#define NSTAGE 4
#define SMEM_TOTAL (NSTAGE * STAGE_BYTES)   // 81920
#define THRESH 2.5e-3f
#define MMAX   32768
#define FIXCAP (1 << 20)

// ---- device scratch ----
__device__ float  g_WT [NDIM * NDIM];            // W^T (n,k), diag=0, fp32 (fixup)
__device__ __half g_Whf[NDIM * NDIM];            // W^T fp16
__device__ __half g_Xh [(size_t)MMAX * NDIM];    // X fp16
__device__ unsigned int g_cnt;
__device__ unsigned int g_list[FIXCAP];

__device__ __forceinline__ uint32_t smem_u32(const void* p) {
    uint32_t a;
    asm("{ .reg .u64 t; cvta.to.shared.u64 t, %1; cvt.u32.u64 %0, t; }" : "=r"(a) : "l"(p));
    return a;
}
__device__ __forceinline__ void mma_fp16(float* c, const uint32_t* a,
                                         uint32_t b0, uint32_t b1) {
    asm volatile(
        "mma.sync.aligned.m16n8k16.row.col.f32.f16.f16.f32 "
        "{%0,%1,%2,%3}, {%4,%5,%6,%7}, {%8,%9}, {%0,%1,%2,%3};\n"
        : "+f"(c[0]), "+f"(c[1]), "+f"(c[2]), "+f"(c[3])
        : "r"(a[0]), "r"(a[1]), "r"(a[2]), "r"(a[3]), "r"(b0), "r"(b1));
}
__device__ __forceinline__ void ldmx4(uint32_t* r, uint32_t addr) {
    asm volatile("ldmatrix.sync.aligned.m8n8.x4.shared.b16 {%0,%1,%2,%3}, [%4];"
        : "=r"(r[0]), "=r"(r[1]), "=r"(r[2]), "=r"(r[3]) : "r"(addr));
}
#define CP16(dst, src) \
    asm volatile("cp.async.cg.shared.global [%0], [%1], 16;\n" :: "r"(dst), "l"(src))
#define CP_COMMIT()  asm volatile("cp.async.commit_group;\n" ::: "memory")
#define CP_WAITG(n)  asm volatile("cp.async.wait_group %0;\n" :: "n"(n) : "memory")

// ============================ prep ============================
__global__ void prep_w(const float* __restrict__ W) {
    int idx = blockIdx.x * blockDim.x + threadIdx.x;   // n*512 + k
    if (idx == 0) g_cnt = 0;
    int n = idx >> 9, k = idx & (NDIM - 1);
    float w = (k == n) ? 0.0f : W[(size_t)k * NDIM + n];
    g_WT[idx]  = w;
    g_Whf[idx] = __float2half_rn(w);
}

__global__ void prep_x(const float* __restrict__ X, int total4) {
    int idx = blockIdx.x * blockDim.x + threadIdx.x;
    if (idx >= total4) return;
    float4 v = reinterpret_cast<const float4*>(X)[idx];
    __half2 h01 = __floats2half2_rn(v.x, v.y);
    __half2 h23 = __floats2half2_rn(v.z, v.w);
    reinterpret_cast<uint2*>(g_Xh)[idx] =
        make_uint2(*reinterpret_cast<uint32_t*>(&h01),
                   *reinterpret_cast<uint32_t*>(&h23));
}

// ============================ main ============================
__global__ __launch_bounds__(NTHREADS, 2)
void li_mma_kernel(const float* __restrict__ X,
                   const float* __restrict__ bias,
                   float* __restrict__ out)
{
    extern __shared__ char smem[];
    const uint32_t sb = smem_u32(smem);
    const int tid = threadIdx.x;
    const int lid = tid & 31;
    const int wid = tid >> 5;
    const int wm  = wid >> 2;          // 0..1
    const int wn  = wid & 3;           // 0..3
    const int g   = lid >> 2;          // 0..7
    const int t   = lid & 3;           // 0..3
    const int q   = lid >> 3;          // 0..3
    const int rl  = lid & 7;           // 0..7
    const int cta_n = blockIdx.x * CTA_N;
    const size_t cta_m = (size_t)blockIdx.y * CTA_M;

    float acc[4][4][4];
    #pragma unroll
    for (int a = 0; a < 4; ++a)
        #pragma unroll
        for (int b = 0; b < 4; ++b)
            #pragma unroll
            for (int c = 0; c < 4; ++c) acc[a][b][c] = 0.0f;

    auto loadStage = [&](int chunk) {
        const uint32_t st = sb + (uint32_t)(chunk & (NSTAGE - 1)) * STAGE_BYTES;
        const char* xh = (const char*)g_Xh;
        const char* wh = (const char*)g_Whf;
        #pragma unroll
        for (int j = 0; j < 2; ++j) {
            int c = tid + j * NTHREADS;       // 0..511
            int row = c >> 2, c4 = c & 3;
            uint32_t doff = row * ROWB + c4 * 16;
            size_t gA = ((cta_m + row) * NDIM + (size_t)chunk * BK) * 2 + c4 * 16;
            size_t gB = (((size_t)cta_n + row) * NDIM + (size_t)chunk * BK) * 2 + c4 * 16;
            CP16(st + doff,         xh + gA);
            CP16(st + TILEB + doff, wh + gB);
        }
        CP_COMMIT();
    };

    auto compute = [&](int chunk) {
        const uint32_t st = sb + (uint32_t)(chunk & (NSTAGE - 1)) * STAGE_BYTES;
        #pragma unroll
        for (int ks = 0; ks < 2; ++ks) {
            uint32_t bh[4][2];
            #pragma unroll
            for (int ntp = 0; ntp < 2; ++ntp) {
                uint32_t baddr = st + TILEB
                    + (uint32_t)(wn * 32 + (ntp * 2 + (q >> 1)) * 8 + rl) * ROWB
                    + ks * 32 + (q & 1) * 16;
                uint32_t rr[4];
                ldmx4(rr, baddr);
                bh[2 * ntp][0] = rr[0]; bh[2 * ntp][1] = rr[1];
                bh[2 * ntp + 1][0] = rr[2]; bh[2 * ntp + 1][1] = rr[3];
            }
            #pragma unroll
            for (int mt = 0; mt < 4; ++mt) {
                uint32_t aaddr = st
                    + (uint32_t)(wm * 64 + mt * 16 + (q & 1) * 8 + rl) * ROWB
                    + ks * 32 + (q >> 1) * 16;
                uint32_t Ah[4];
                ldmx4(Ah, aaddr);
                #pragma unroll
                for (int nt = 0; nt < 4; ++nt)
                    mma_fp16(acc[mt][nt], Ah, bh[nt][0], bh[nt][1]);
            }
        }
    };

    // ---- 4-stage pipeline ----
    loadStage(0); loadStage(1); loadStage(2);
    for (int i = 0; i < NCH; ++i) {
        if (i + 3 < NCH) { CP_WAITG(2); } else { CP_WAITG(0); }
        __syncthreads();
        compute(i);
        if (i + 3 < NCH) loadStage(i + 3);
    }

    // ---- epilogue: bias + gate; flag tiny |inhib| into worklist ----
    #pragma unroll
    for (int mt = 0; mt < 4; ++mt) {
        #pragma unroll
        for (int nt = 0; nt < 4; ++nt) {
            const int gcol = cta_n + wn * 32 + nt * 8 + 2 * t;
            const float b0 = bias[gcol], b1 = bias[gcol + 1];
            #pragma unroll
            for (int half = 0; half < 2; ++half) {
                const size_t grow = cta_m + wm * 64 + mt * 16 + g + half * 8;
                const float v0 = acc[mt][nt][half * 2 + 0] + b0;
                const float v1 = acc[mt][nt][half * 2 + 1] + b1;
                if (fabsf(v0) < THRESH) {
                    unsigned int s = atomicAdd(&g_cnt, 1u);
                    if (s < FIXCAP) g_list[s] = (unsigned int)(grow * NDIM + gcol);
                }
                if (fabsf(v1) < THRESH) {
                    unsigned int s = atomicAdd(&g_cnt, 1u);
                    if (s < FIXCAP) g_list[s] = (unsigned int)(grow * NDIM + gcol + 1);
                }
                const float2 xv = *reinterpret_cast<const float2*>(
                    X + grow * NDIM + gcol);
                float2 o;
                o.x = v0 > 0.0f ? xv.x : 0.0f;
                o.y = v1 > 0.0f ? xv.y : 0.0f;
                *reinterpret_cast<float2*>(out + grow * NDIM + gcol) = o;
            }
        }
    }
}

// ============================ fixup ============================
__global__ void li_fixup(const float* __restrict__ X,
                         const float* __restrict__ bias,
                         float* __restrict__ out)
{
    const unsigned int cnt = min(g_cnt, (unsigned int)FIXCAP);
    const int lid = threadIdx.x & 31;
    const unsigned int gwarp = (blockIdx.x * blockDim.x + threadIdx.x) >> 5;
    const unsigned int nwarp = (gridDim.x * blockDim.x) >> 5;
    for (unsigned int j = gwarp; j < cnt; j += nwarp) {
        const unsigned int e = g_list[j];
        const unsigned int row = e >> 9;
        const unsigned int col = e & (NDIM - 1);
        const float* xr = X + (size_t)row * NDIM;
        const float* wr = g_WT + (size_t)col * NDIM;
        float s = 0.0f;
        #pragma unroll
        for (int k = 0; k < NDIM / 32; ++k)
            s = fmaf(xr[lid + k * 32], wr[lid + k * 32], s);
        #pragma unroll
        for (int off = 16; off > 0; off >>= 1)
            s += __shfl_xor_sync(0xFFFFFFFF, s, off);
        if (lid == 0) {
            const float v = s + bias[col];
            out[(size_t)row * NDIM + col] = v > 0.0f ? xr[col] : 0.0f;
        }
    }
}

// ============================ host ============================
extern "C" void kernel_launch(void* const* d_in, const int* in_sizes, int n_in,
                              void* d_out, int out_size)
{
    const float* X    = (const float*)d_in[0];
    const float* W    = (const float*)d_in[1];
    const float* bias = (const float*)d_in[2];
    float* out = (float*)d_out;
    const int M = in_sizes[0] / NDIM;   // 32768

    prep_w<<<(NDIM * NDIM) / 256, 256>>>(W);
    const int total4 = M * NDIM / 4;
    prep_x<<<(total4 + 255) / 256, 256>>>(X, total4);

    cudaFuncSetAttribute(li_mma_kernel,
                         cudaFuncAttributeMaxDynamicSharedMemorySize, SMEM_TOTAL);
    dim3 grid(NDIM / CTA_N, M / CTA_M);   // (4, 256)
    li_mma_kernel<<<grid, NTHREADS, SMEM_TOTAL>>>(X, bias, out);

    li_fixup<<<512, 256>>>(X, bias, out);
}

// round 7
// speedup vs baseline: 2.7000x; 1.1130x over previous
#include <cuda_runtime.h>
#include <cuda_fp16.h>
#include <cstdint>

#define NDIM   512
#define BK     32
#define NCH    (NDIM / BK)          // 16
#define CTA_M  128
#define CTA_N  128
#define NTHREADS 256
#define ROWB   80                   // padded smem row stride (32 fp16 = 64B + 16B pad)
#define TILEB  (128 * ROWB)         // 10240 B
#define STAGE_BYTES (2 * TILEB)     // A + B = 20480
#define NSTAGE 4
#define SMEM_TOTAL (NSTAGE * STAGE_BYTES)   // 81920
#define THRESH 2.5e-3f
#define MMAX   32768
#define FIXCAP (1 << 20)

// ---- device scratch ----
__device__ float  g_WT [NDIM * NDIM];            // W^T (n,k), diag=0, fp32 (fixup)
__device__ __half g_Whf[NDIM * NDIM];            // W^T fp16
__device__ __half g_Xh [(size_t)MMAX * NDIM];    // X fp16
__device__ unsigned int g_cnt;
__device__ unsigned int g_list[FIXCAP];

__device__ __forceinline__ uint32_t smem_u32(const void* p) {
    uint32_t a;
    asm("{ .reg .u64 t; cvta.to.shared.u64 t, %1; cvt.u32.u64 %0, t; }" : "=r"(a) : "l"(p));
    return a;
}
__device__ __forceinline__ void mma_fp16(float* c, const uint32_t* a,
                                         uint32_t b0, uint32_t b1) {
    asm volatile(
        "mma.sync.aligned.m16n8k16.row.col.f32.f16.f16.f32 "
        "{%0,%1,%2,%3}, {%4,%5,%6,%7}, {%8,%9}, {%0,%1,%2,%3};\n"
        : "+f"(c[0]), "+f"(c[1]), "+f"(c[2]), "+f"(c[3])
        : "r"(a[0]), "r"(a[1]), "r"(a[2]), "r"(a[3]), "r"(b0), "r"(b1));
}
__device__ __forceinline__ void ldmx4(uint32_t* r, uint32_t addr) {
    asm volatile("ldmatrix.sync.aligned.m8n8.x4.shared.b16 {%0,%1,%2,%3}, [%4];"
        : "=r"(r[0]), "=r"(r[1]), "=r"(r[2]), "=r"(r[3]) : "r"(addr));
}
#define CP16(dst, src) \
    asm volatile("cp.async.cg.shared.global [%0], [%1], 16;\n" :: "r"(dst), "l"(src))
#define CP_COMMIT()  asm volatile("cp.async.commit_group;\n" ::: "memory")
#define CP_WAITG(n)  asm volatile("cp.async.wait_group %0;\n" :: "n"(n) : "memory")

// ============================ prep ============================
__global__ void prep_w(const float* __restrict__ W) {
    int idx = blockIdx.x * blockDim.x + threadIdx.x;   // n*512 + k
    if (idx == 0) g_cnt = 0;
    int n = idx >> 9, k = idx & (NDIM - 1);
    float w = (k == n) ? 0.0f : W[(size_t)k * NDIM + n];
    g_WT[idx]  = w;
    g_Whf[idx] = __float2half_rn(w);
}

__global__ void prep_x(const float* __restrict__ X, int total4) {
    int idx = blockIdx.x * blockDim.x + threadIdx.x;
    if (idx >= total4) return;
    float4 v = reinterpret_cast<const float4*>(X)[idx];
    __half2 h01 = __floats2half2_rn(v.x, v.y);
    __half2 h23 = __floats2half2_rn(v.z, v.w);
    reinterpret_cast<uint2*>(g_Xh)[idx] =
        make_uint2(*reinterpret_cast<uint32_t*>(&h01),
                   *reinterpret_cast<uint32_t*>(&h23));
}

// ============================ main ============================
__global__ __launch_bounds__(NTHREADS, 2)
void li_mma_kernel(const float* __restrict__ X,
                   const float* __restrict__ bias,
                   float* __restrict__ out)
{
    extern __shared__ char smem[];
    const uint32_t sb = smem_u32(smem);
    const int tid = threadIdx.x;
    const int lid = tid & 31;
    const int wid = tid >> 5;
    const int wm  = wid >> 2;          // 0..1
    const int wn  = wid & 3;           // 0..3
    const int g   = lid >> 2;          // 0..7
    const int t   = lid & 3;           // 0..3
    const int q   = lid >> 3;          // 0..3
    const int rl  = lid & 7;           // 0..7
    const int cta_n = blockIdx.x * CTA_N;
    const size_t cta_m = (size_t)blockIdx.y * CTA_M;

    float acc[4][4][4];
    #pragma unroll
    for (int a = 0; a < 4; ++a)
        #pragma unroll
        for (int b = 0; b < 4; ++b)
            #pragma unroll
            for (int c = 0; c < 4; ++c) acc[a][b][c] = 0.0f;

    auto loadStage = [&](int chunk) {
        const uint32_t st = sb + (uint32_t)(chunk & (NSTAGE - 1)) * STAGE_BYTES;
        const char* xh = (const char*)g_Xh;
        const char* wh = (const char*)g_Whf;
        #pragma unroll
        for (int j = 0; j < 2; ++j) {
            int c = tid + j * NTHREADS;       // 0..511
            int row = c >> 2, c4 = c & 3;
            uint32_t doff = row * ROWB + c4 * 16;
            size_t gA = ((cta_m + row) * NDIM + (size_t)chunk * BK) * 2 + c4 * 16;
            size_t gB = (((size_t)cta_n + row) * NDIM + (size_t)chunk * BK) * 2 + c4 * 16;
            CP16(st + doff,         xh + gA);
            CP16(st + TILEB + doff, wh + gB);
        }
        CP_COMMIT();
    };

    auto compute = [&](int chunk) {
        const uint32_t st = sb + (uint32_t)(chunk & (NSTAGE - 1)) * STAGE_BYTES;
        #pragma unroll
        for (int ks = 0; ks < 2; ++ks) {
            uint32_t bh[4][2];
            #pragma unroll
            for (int ntp = 0; ntp < 2; ++ntp) {
                uint32_t baddr = st + TILEB
                    + (uint32_t)(wn * 32 + (ntp * 2 + (q >> 1)) * 8 + rl) * ROWB
                    + ks * 32 + (q & 1) * 16;
                uint32_t rr[4];
                ldmx4(rr, baddr);
                bh[2 * ntp][0] = rr[0]; bh[2 * ntp][1] = rr[1];
                bh[2 * ntp + 1][0] = rr[2]; bh[2 * ntp + 1][1] = rr[3];
            }
            #pragma unroll
            for (int mt = 0; mt < 4; ++mt) {
                uint32_t aaddr = st
                    + (uint32_t)(wm * 64 + mt * 16 + (q & 1) * 8 + rl) * ROWB
                    + ks * 32 + (q >> 1) * 16;
                uint32_t Ah[4];
                ldmx4(Ah, aaddr);
                #pragma unroll
                for (int nt = 0; nt < 4; ++nt)
                    mma_fp16(acc[mt][nt], Ah, bh[nt][0], bh[nt][1]);
            }
        }
    };

    // ---- 4-stage pipeline ----
    loadStage(0); loadStage(1); loadStage(2);
    for (int i = 0; i < NCH; ++i) {
        if (i + 3 < NCH) { CP_WAITG(2); } else { CP_WAITG(0); }
        __syncthreads();
        compute(i);
        if (i + 3 < NCH) loadStage(i + 3);
    }

    // ---- epilogue: bias + gate; flag tiny |inhib| into worklist ----
    #pragma unroll
    for (int mt = 0; mt < 4; ++mt) {
        #pragma unroll
        for (int nt = 0; nt < 4; ++nt) {
            const int gcol = cta_n + wn * 32 + nt * 8 + 2 * t;
            const float b0 = bias[gcol], b1 = bias[gcol + 1];
            #pragma unroll
            for (int half = 0; half < 2; ++half) {
                const size_t grow = cta_m + wm * 64 + mt * 16 + g + half * 8;
                const float v0 = acc[mt][nt][half * 2 + 0] + b0;
                const float v1 = acc[mt][nt][half * 2 + 1] + b1;
                if (fabsf(v0) < THRESH) {
                    unsigned int s = atomicAdd(&g_cnt, 1u);
                    if (s < FIXCAP) g_list[s] = (unsigned int)(grow * NDIM + gcol);
                }
                if (fabsf(v1) < THRESH) {
                    unsigned int s = atomicAdd(&g_cnt, 1u);
                    if (s < FIXCAP) g_list[s] = (unsigned int)(grow * NDIM + gcol + 1);
                }
                const float2 xv = *reinterpret_cast<const float2*>(
                    X + grow * NDIM + gcol);
                float2 o;
                o.x = v0 > 0.0f ? xv.x : 0.0f;
                o.y = v1 > 0.0f ? xv.y : 0.0f;
                *reinterpret_cast<float2*>(out + grow * NDIM + gcol) = o;
            }
        }
    }
}

// ============================ fixup (4-way ILP) ============================
__global__ void li_fixup(const float* __restrict__ X,
                         const float* __restrict__ bias,
                         float* __restrict__ out)
{
    const unsigned int cnt = min(g_cnt, (unsigned int)FIXCAP);
    if (cnt == 0) return;
    const int lid = threadIdx.x & 31;
    const unsigned int gwarp = (blockIdx.x * blockDim.x + threadIdx.x) >> 5;
    const unsigned int nwarp = (gridDim.x * blockDim.x) >> 5;

    for (unsigned int base = gwarp * 4; base < cnt; base += nwarp * 4) {
        unsigned int e[4];
        const float* xr[4];
        const float* wr[4];
        #pragma unroll
        for (int u = 0; u < 4; ++u) {
            unsigned int j = base + u;
            e[u] = g_list[j < cnt ? j : cnt - 1];   // clamp: duplicate recompute is idempotent
            xr[u] = X + (size_t)(e[u] >> 9) * NDIM;
            wr[u] = g_WT + (size_t)(e[u] & (NDIM - 1)) * NDIM;
        }
        float s[4] = {0.0f, 0.0f, 0.0f, 0.0f};
        #pragma unroll
        for (int k = 0; k < NDIM / 32; ++k) {
            const int kk = lid + k * 32;
            #pragma unroll
            for (int u = 0; u < 4; ++u)
                s[u] = fmaf(xr[u][kk], wr[u][kk], s[u]);
        }
        #pragma unroll
        for (int u = 0; u < 4; ++u) {
            #pragma unroll
            for (int off = 16; off > 0; off >>= 1)
                s[u] += __shfl_xor_sync(0xFFFFFFFF, s[u], off);
        }
        if (lid == 0) {
            #pragma unroll
            for (int u = 0; u < 4; ++u) {
                const unsigned int col = e[u] & (NDIM - 1);
                const float v = s[u] + bias[col];
                out[(size_t)e[u]] = v > 0.0f ? xr[u][col] : 0.0f;
            }
        }
    }
}

// ============================ host ============================
extern "C" void kernel_launch(void* const* d_in, const int* in_sizes, int n_in,
                              void* d_out, int out_size)
{
    const float* X    = (const float*)d_in[0];
    const float* W    = (const float*)d_in[1];
    const float* bias = (const float*)d_in[2];
    float* out = (float*)d_out;
    const int M = in_sizes[0] / NDIM;   // 32768

    prep_w<<<(NDIM * NDIM) / 256, 256>>>(W);
    const int total4 = M * NDIM / 4;
    prep_x<<<(total4 + 255) / 256, 256>>>(X, total4);

    cudaFuncSetAttribute(li_mma_kernel,
                         cudaFuncAttributeMaxDynamicSharedMemorySize, SMEM_TOTAL);
    dim3 grid(NDIM / CTA_N, M / CTA_M);   // (4, 256)
    li_mma_kernel<<<grid, NTHREADS, SMEM_TOTAL>>>(X, bias, out);

    li_fixup<<<1024, 256>>>(X, bias, out);
}

// round 8
// speedup vs baseline: 3.9576x; 1.4657x over previous
#include <cuda_runtime.h>
#include <cuda_fp16.h>
#include <cstdint>

#define NDIM   512
#define BK     32
#define NCH    (NDIM / BK)          // 16
#define CTA_M  128
#define CTA_N  128
#define NTHREADS 256
#define ROWB   80                   // padded smem row stride (32 fp16 = 64B + 16B pad)
#define TILEB  (128 * ROWB)         // 10240 B
#define STAGE_BYTES (2 * TILEB)     // A + B = 20480
#define NSTAGE 4
#define SMEM_TOTAL (NSTAGE * STAGE_BYTES)   // 81920
#define THRESH 1e-3f
#define MMAX   32768
#define FIXCAP (1 << 20)

// ---- device scratch ----
__device__ float  g_WT [NDIM * NDIM];            // W^T (n,k), diag=0, fp32 (fixup)
__device__ __half g_Whf[NDIM * NDIM];            // W^T fp16
__device__ __half g_Xh [(size_t)MMAX * NDIM];    // X fp16
__device__ unsigned int g_cnt;
__device__ unsigned int g_list[FIXCAP];

__device__ __forceinline__ uint32_t smem_u32(const void* p) {
    uint32_t a;
    asm("{ .reg .u64 t; cvta.to.shared.u64 t, %1; cvt.u32.u64 %0, t; }" : "=r"(a) : "l"(p));
    return a;
}
__device__ __forceinline__ void mma_fp16(float* c, const uint32_t* a,
                                         uint32_t b0, uint32_t b1) {
    asm volatile(
        "mma.sync.aligned.m16n8k16.row.col.f32.f16.f16.f32 "
        "{%0,%1,%2,%3}, {%4,%5,%6,%7}, {%8,%9}, {%0,%1,%2,%3};\n"
        : "+f"(c[0]), "+f"(c[1]), "+f"(c[2]), "+f"(c[3])
        : "r"(a[0]), "r"(a[1]), "r"(a[2]), "r"(a[3]), "r"(b0), "r"(b1));
}
__device__ __forceinline__ void ldmx4(uint32_t* r, uint32_t addr) {
    asm volatile("ldmatrix.sync.aligned.m8n8.x4.shared.b16 {%0,%1,%2,%3}, [%4];"
        : "=r"(r[0]), "=r"(r[1]), "=r"(r[2]), "=r"(r[3]) : "r"(addr));
}
#define CP16(dst, src) \
    asm volatile("cp.async.cg.shared.global [%0], [%1], 16;\n" :: "r"(dst), "l"(src))
#define CP_COMMIT()  asm volatile("cp.async.commit_group;\n" ::: "memory")
#define CP_WAITG(n)  asm volatile("cp.async.wait_group %0;\n" :: "n"(n) : "memory")

// ============================ prep ============================
__global__ void prep_w(const float* __restrict__ W) {
    int idx = blockIdx.x * blockDim.x + threadIdx.x;   // n*512 + k
    if (idx == 0) g_cnt = 0;
    int n = idx >> 9, k = idx & (NDIM - 1);
    float w = (k == n) ? 0.0f : W[(size_t)k * NDIM + n];
    g_WT[idx]  = w;
    g_Whf[idx] = __float2half_rn(w);
}

__global__ void prep_x(const float* __restrict__ X, int total4) {
    int idx = blockIdx.x * blockDim.x + threadIdx.x;
    if (idx >= total4) return;
    float4 v = reinterpret_cast<const float4*>(X)[idx];
    __half2 h01 = __floats2half2_rn(v.x, v.y);
    __half2 h23 = __floats2half2_rn(v.z, v.w);
    reinterpret_cast<uint2*>(g_Xh)[idx] =
        make_uint2(*reinterpret_cast<uint32_t*>(&h01),
                   *reinterpret_cast<uint32_t*>(&h23));
}

// ============================ main ============================
__global__ __launch_bounds__(NTHREADS, 2)
void li_mma_kernel(const float* __restrict__ X,
                   const float* __restrict__ bias,
                   float* __restrict__ out)
{
    extern __shared__ char smem[];
    const uint32_t sb = smem_u32(smem);
    const int tid = threadIdx.x;
    const int lid = tid & 31;
    const int wid = tid >> 5;
    const int wm  = wid >> 2;          // 0..1
    const int wn  = wid & 3;           // 0..3
    const int g   = lid >> 2;          // 0..7
    const int t   = lid & 3;           // 0..3
    const int q   = lid >> 3;          // 0..3
    const int rl  = lid & 7;           // 0..7
    const int cta_n = blockIdx.x * CTA_N;
    const size_t cta_m = (size_t)blockIdx.y * CTA_M;

    float acc[4][4][4];
    #pragma unroll
    for (int a = 0; a < 4; ++a)
        #pragma unroll
        for (int b = 0; b < 4; ++b)
            #pragma unroll
            for (int c = 0; c < 4; ++c) acc[a][b][c] = 0.0f;

    auto loadStage = [&](int chunk) {
        const uint32_t st = sb + (uint32_t)(chunk & (NSTAGE - 1)) * STAGE_BYTES;
        const char* xh = (const char*)g_Xh;
        const char* wh = (const char*)g_Whf;
        #pragma unroll
        for (int j = 0; j < 2; ++j) {
            int c = tid + j * NTHREADS;       // 0..511
            int row = c >> 2, c4 = c & 3;
            uint32_t doff = row * ROWB + c4 * 16;
            size_t gA = ((cta_m + row) * NDIM + (size_t)chunk * BK) * 2 + c4 * 16;
            size_t gB = (((size_t)cta_n + row) * NDIM + (size_t)chunk * BK) * 2 + c4 * 16;
            CP16(st + doff,         xh + gA);
            CP16(st + TILEB + doff, wh + gB);
        }
        CP_COMMIT();
    };

    auto compute = [&](int chunk) {
        const uint32_t st = sb + (uint32_t)(chunk & (NSTAGE - 1)) * STAGE_BYTES;
        #pragma unroll
        for (int ks = 0; ks < 2; ++ks) {
            uint32_t bh[4][2];
            #pragma unroll
            for (int ntp = 0; ntp < 2; ++ntp) {
                uint32_t baddr = st + TILEB
                    + (uint32_t)(wn * 32 + (ntp * 2 + (q >> 1)) * 8 + rl) * ROWB
                    + ks * 32 + (q & 1) * 16;
                uint32_t rr[4];
                ldmx4(rr, baddr);
                bh[2 * ntp][0] = rr[0]; bh[2 * ntp][1] = rr[1];
                bh[2 * ntp + 1][0] = rr[2]; bh[2 * ntp + 1][1] = rr[3];
            }
            #pragma unroll
            for (int mt = 0; mt < 4; ++mt) {
                uint32_t aaddr = st
                    + (uint32_t)(wm * 64 + mt * 16 + (q & 1) * 8 + rl) * ROWB
                    + ks * 32 + (q >> 1) * 16;
                uint32_t Ah[4];
                ldmx4(Ah, aaddr);
                #pragma unroll
                for (int nt = 0; nt < 4; ++nt)
                    mma_fp16(acc[mt][nt], Ah, bh[nt][0], bh[nt][1]);
            }
        }
    };

    // ---- 4-stage pipeline ----
    loadStage(0); loadStage(1); loadStage(2);
    for (int i = 0; i < NCH; ++i) {
        if (i + 3 < NCH) { CP_WAITG(2); } else { CP_WAITG(0); }
        __syncthreads();
        compute(i);
        if (i + 3 < NCH) loadStage(i + 3);
    }

    // ---- epilogue: bias + gate; flag tiny |inhib| into worklist ----
    #pragma unroll
    for (int mt = 0; mt < 4; ++mt) {
        #pragma unroll
        for (int nt = 0; nt < 4; ++nt) {
            const int gcol = cta_n + wn * 32 + nt * 8 + 2 * t;
            const float b0 = bias[gcol], b1 = bias[gcol + 1];
            #pragma unroll
            for (int half = 0; half < 2; ++half) {
                const size_t grow = cta_m + wm * 64 + mt * 16 + g + half * 8;
                const float v0 = acc[mt][nt][half * 2 + 0] + b0;
                const float v1 = acc[mt][nt][half * 2 + 1] + b1;
                if (fabsf(v0) < THRESH) {
                    unsigned int s = atomicAdd(&g_cnt, 1u);
                    if (s < FIXCAP) g_list[s] = (unsigned int)(grow * NDIM + gcol);
                }
                if (fabsf(v1) < THRESH) {
                    unsigned int s = atomicAdd(&g_cnt, 1u);
                    if (s < FIXCAP) g_list[s] = (unsigned int)(grow * NDIM + gcol + 1);
                }
                const float2 xv = *reinterpret_cast<const float2*>(
                    X + grow * NDIM + gcol);
                float2 o;
                o.x = v0 > 0.0f ? xv.x : 0.0f;
                o.y = v1 > 0.0f ? xv.y : 0.0f;
                *reinterpret_cast<float2*>(out + grow * NDIM + gcol) = o;
            }
        }
    }
}

// ============================ fixup (float4, 4-way ILP) ============================
__global__ void li_fixup(const float* __restrict__ X,
                         const float* __restrict__ bias,
                         float* __restrict__ out)
{
    const unsigned int cnt = min(g_cnt, (unsigned int)FIXCAP);
    if (cnt == 0) return;
    const int lid = threadIdx.x & 31;
    const unsigned int gwarp = (blockIdx.x * blockDim.x + threadIdx.x) >> 5;
    const unsigned int nwarp = (gridDim.x * blockDim.x) >> 5;

    for (unsigned int base = gwarp * 4; base < cnt; base += nwarp * 4) {
        unsigned int e[4];
        const float4* xr[4];
        const float4* wr[4];
        #pragma unroll
        for (int u = 0; u < 4; ++u) {
            unsigned int j = base + u;
            e[u] = g_list[j < cnt ? j : cnt - 1];   // clamp: duplicate recompute is idempotent
            xr[u] = reinterpret_cast<const float4*>(X + (size_t)(e[u] >> 9) * NDIM);
            wr[u] = reinterpret_cast<const float4*>(g_WT + (size_t)(e[u] & (NDIM - 1)) * NDIM);
        }
        float s[4] = {0.0f, 0.0f, 0.0f, 0.0f};
        #pragma unroll
        for (int k = 0; k < NDIM / 128; ++k) {       // 4 iterations of float4
            const int f4 = k * 32 + lid;
            float4 xv[4], wv[4];
            #pragma unroll
            for (int u = 0; u < 4; ++u) { xv[u] = xr[u][f4]; wv[u] = wr[u][f4]; }
            #pragma unroll
            for (int u = 0; u < 4; ++u) {
                s[u] = fmaf(xv[u].x, wv[u].x, s[u]);
                s[u] = fmaf(xv[u].y, wv[u].y, s[u]);
                s[u] = fmaf(xv[u].z, wv[u].z, s[u]);
                s[u] = fmaf(xv[u].w, wv[u].w, s[u]);
            }
        }
        #pragma unroll
        for (int u = 0; u < 4; ++u) {
            #pragma unroll
            for (int off = 16; off > 0; off >>= 1)
                s[u] += __shfl_xor_sync(0xFFFFFFFF, s[u], off);
        }
        if (lid == 0) {
            #pragma unroll
            for (int u = 0; u < 4; ++u) {
                const unsigned int col = e[u] & (NDIM - 1);
                const float v = s[u] + bias[col];
                out[(size_t)e[u]] = v > 0.0f
                    ? X[(size_t)(e[u] >> 9) * NDIM + col] : 0.0f;
            }
        }
    }
}

// ============================ host ============================
extern "C" void kernel_launch(void* const* d_in, const int* in_sizes, int n_in,
                              void* d_out, int out_size)
{
    const float* X    = (const float*)d_in[0];
    const float* W    = (const float*)d_in[1];
    const float* bias = (const float*)d_in[2];
    float* out = (float*)d_out;
    const int M = in_sizes[0] / NDIM;   // 32768

    prep_w<<<(NDIM * NDIM) / 256, 256>>>(W);
    const int total4 = M * NDIM / 4;
    prep_x<<<(total4 + 255) / 256, 256>>>(X, total4);

    cudaFuncSetAttribute(li_mma_kernel,
                         cudaFuncAttributeMaxDynamicSharedMemorySize, SMEM_TOTAL);
    dim3 grid(NDIM / CTA_N, M / CTA_M);   // (4, 256)
    li_mma_kernel<<<grid, NTHREADS, SMEM_TOTAL>>>(X, bias, out);

    li_fixup<<<1024, 256>>>(X, bias, out);
}